// round 7
// baseline (speedup 1.0000x reference)
#include <cuda_runtime.h>
#include <stdint.h>

#define BATCH  8
#define NANCH  100800
#define KPRE   1024
#define MAXDET 100
#define GRID   148
#define TILEA  192                      // 525 * 192 == 100800
#define NTILES (BATCH * 525)            // 4200
#define N4     (NANCH / 4)              // 25200

// ---------------- scratch (static device memory; no runtime allocation) ------
__device__ unsigned int        g_ukey[BATCH][NANCH];
__device__ unsigned char       g_cls [BATCH][NANCH];
__device__ unsigned int        g_hist[BATCH][2048];     // self-zeroing each run
__device__ unsigned long long  g_cand[BATCH][NANCH];    // pivot-bin candidates
__device__ unsigned int        g_arrive;                // grid barrier (self-reset)
__device__ unsigned int        g_wpass;                 // worker completion count

// ---------------- shared memory union ----------------------------------------
struct SmemB {
    unsigned hist[2048];
    unsigned long long selKey[KPRE];    // sort buffer 0
    unsigned long long sbuf1[KPRE];     // eqIdx storage + sort buffer 1
    float s0[KPRE], s1[KPRE], s2[KPRE], s3[KPRE], sar[KPRE];  // offset boxes
    float bx1[KPRE], by1[KPRE], bx2[KPRE], by2[KPRE];         // raw boxes
    float ssc[KPRE], scf[KPRE];
    unsigned smask[32][32];             // lazy mask chunk: 32 rows x 32 words
    unsigned chunkSum[64];
    unsigned sres[2];
    int list[MAXDET];
    int cntGt, cntEq, cntCand, skc;
};
union SmemU {
    SmemB nms;
    float tile[TILEA * 85];             // 16320 floats = 65280 B (phase 1)
};

// ---------------- helpers -----------------------------------------------------
__device__ __forceinline__ int wappend(int* ctr, bool p)
{
    unsigned m = __ballot_sync(0xFFFFFFFFu, p);
    int pos = -1;
    if (p) {
        int l = threadIdx.x & 31;
        int leader = __ffs(m) - 1;
        int base = 0;
        if (l == leader) base = atomicAdd(ctr, __popc(m));
        base = __shfl_sync(m, base, leader);
        pos = base + __popc(m & ((1u << l) - 1));
    }
    return pos;
}

__device__ __forceinline__ void hist_add(unsigned* hist, unsigned bin, bool q)
{
    unsigned qm = __ballot_sync(0xFFFFFFFFu, q);
    if (q) {
        unsigned peers = __match_any_sync(qm, bin);
        int ld = __ffs(peers) - 1;
        if ((int)(threadIdx.x & 31) == ld) atomicAdd(&hist[bin], (unsigned)__popc(peers));
    }
}

__device__ __forceinline__ void find_bin(unsigned* hist, unsigned* chunkSum,
                                         int NB, unsigned K, unsigned* sres, int tid)
{
    int nch = NB >> 5;
    if (tid < nch) {
        unsigned s = 0;
        int base = tid << 5;
#pragma unroll 8
        for (int i = 0; i < 32; ++i) s += hist[base + i];
        chunkSum[tid] = s;
    }
    __syncthreads();
    if (tid == 0) {
        unsigned acc = 0;
        int c = nch - 1;
        for (;; --c) {
            unsigned cs = chunkSum[c];
            if (acc + cs >= K) break;
            acc += cs;
        }
        int bin = (c << 5) + 31;
        for (;; --bin) {
            unsigned hv = hist[bin];
            if (acc + hv >= K) break;
            acc += hv;
        }
        sres[0] = (unsigned)bin;
        sres[1] = acc;          // count strictly above bin
    }
    __syncthreads();
}

__device__ __forceinline__ unsigned long long umaxll(unsigned long long a, unsigned long long b)
{ return a > b ? a : b; }
__device__ __forceinline__ unsigned long long uminll(unsigned long long a, unsigned long long b)
{ return a < b ? a : b; }

// ---------------- the single fused kernel -------------------------------------
__global__ void __launch_bounds__(1024, 1) k_all(const float* __restrict__ pred,
                                                 float* __restrict__ out)
{
    extern __shared__ unsigned char dyn[];
    SmemU* smu = (SmemU*)dyn;
    float* smf = smu->tile;

    int tid = threadIdx.x;
    int l = tid & 31, warp = tid >> 5;

    // ============ PHASE 1: score / argmax / key / histogram (all CTAs) =======
    for (int T = blockIdx.x; T < NTILES; T += GRID) {
        int b = T / 525;
        int astart = (T % 525) * TILEA;
        const float4* p4 = (const float4*)(pred + ((size_t)b * NANCH + astart) * 85);
        float4* t4 = (float4*)smf;
#pragma unroll
        for (int k = 0; k < 4; ++k) {
            int idx = k * 1024 + tid;
            if (idx < TILEA * 85 / 4) t4[idx] = p4[idx];
        }
        __syncthreads();

        if (tid < TILEA * 4) {              // 4 threads per anchor (768 active)
            int a = tid >> 2, ch = tid & 3;
            const float* row = smf + a * 85;
            float obj = row[4];
            float v = __fmul_rn(row[5 + ch], obj);
            int bi = ch;
#pragma unroll
            for (int c = ch + 4; c < 80; c += 4) {
                float x = __fmul_rn(row[5 + c], obj);
                if (x > v) { v = x; bi = c; }      // strict > == first in chain
            }
            // symmetric merge across the 4-lane group: (value, then lower idx)
#pragma unroll
            for (int off = 1; off < 4; off <<= 1) {
                float ov = __shfl_xor_sync(0xFFFFFFFFu, v, off);
                int   oi = __shfl_xor_sync(0xFFFFFFFFu, bi, off);
                if (ov > v || (ov == v && oi < bi)) { v = ov; bi = oi; }
            }
            if (ch == 0) {
                bool  valid = (obj > 0.25f) && (v > 0.25f);
                float smv = valid ? v : -1.0f;
                int   sb = __float_as_int(smv);
                unsigned u = (unsigned)sb ^ ((sb < 0) ? 0xFFFFFFFFu : 0x80000000u);
                int n = astart + a;
                g_ukey[b][n] = u;
                g_cls [b][n] = (unsigned char)bi;
                atomicAdd(&g_hist[b][u >> 21], 1u);
            }
        }
        __syncthreads();
    }

    // ============ grid barrier (all 148 CTAs resident by construction) =======
    __syncthreads();
    if (tid == 0) { __threadfence(); atomicAdd(&g_arrive, 1u); }
    if (blockIdx.x >= BATCH) return;        // non-workers done
    if (tid == 0) {
        while (atomicAdd(&g_arrive, 0u) < (unsigned)GRID) __nanosleep(64);
        __threadfence();
    }
    __syncthreads();

    // ============ PHASE 2: select + sort + gather + lazy-mask NMS ============
    SmemB* sm = &smu->nms;
    int b = blockIdx.x;
    const uint4* uk4 = (const uint4*)&g_ukey[b][0];
    unsigned long long* cand = &g_cand[b][0];
    int* eqIdx = (int*)sm->sbuf1;

    // ---- pass A: histogram from phase 1 (load + self-zero for next run) ----
    sm->hist[tid] = g_hist[b][tid];
    sm->hist[tid + 1024] = g_hist[b][tid + 1024];
    __syncthreads();
    g_hist[b][tid] = 0; g_hist[b][tid + 1024] = 0;
    find_bin(sm->hist, sm->chunkSum, 2048, KPRE, sm->sres, tid);
    unsigned b1 = sm->sres[0], gt1 = sm->sres[1], K1 = KPRE - gt1;
    int C = (int)sm->hist[b1];
    if (tid == 0) { sm->cntGt = 0; sm->cntEq = 0; sm->cntCand = 0; }
    __syncthreads();

    // ---- single key scan: compact sure-winners + pivot-bin candidates ----
    for (int it = 0; it < 25; ++it) {       // uniform trips (warp-sync safe)
        int t = (it << 10) + tid;
        bool act = t < N4;
        uint4 q = act ? uk4[t] : make_uint4(0u, 0u, 0u, 0u);
        unsigned uu[4] = {q.x, q.y, q.z, q.w};
#pragma unroll
        for (int j = 0; j < 4; ++j) {
            unsigned u = uu[j];
            unsigned hb = u >> 21;
            int n = 4 * t + j;
            unsigned long long key = ((unsigned long long)u << 32) | (unsigned)(~n);
            bool isGt = act && (hb > b1);
            int p = wappend(&sm->cntGt, isGt);
            if (isGt) sm->selKey[p] = key;
            bool isEq = act && (hb == b1);
            int p2 = wappend(&sm->cntCand, isEq);
            if (isEq) cand[p2] = key;
        }
    }
    __syncthreads();

    // ---- pass B: mid 11 bits over candidates only ----
    sm->hist[tid] = 0; sm->hist[tid + 1024] = 0;
    __syncthreads();
    int iters = (C + 1023) >> 10;           // uniform across ALL threads
    for (int it = 0; it < iters; ++it) {
        int t = (it << 10) + tid;
        bool act = t < C;
        unsigned long long k = act ? cand[t] : 0ull;
        unsigned u = (unsigned)(k >> 32);
        hist_add(sm->hist, (u >> 10) & 2047u, act);
    }
    __syncthreads();
    find_bin(sm->hist, sm->chunkSum, 2048, K1, sm->sres, tid);
    unsigned b2 = sm->sres[0], gt2 = sm->sres[1], K2 = K1 - gt2;
    __syncthreads();

    // ---- pass C: low 10 bits over candidates matching b2 ----
    sm->hist[tid] = 0;
    __syncthreads();
    for (int it = 0; it < iters; ++it) {
        int t = (it << 10) + tid;
        bool act = t < C;
        unsigned long long k = act ? cand[t] : 0ull;
        unsigned u = (unsigned)(k >> 32);
        hist_add(sm->hist, u & 1023u, act && (((u >> 10) & 2047u) == b2));
    }
    __syncthreads();
    find_bin(sm->hist, sm->chunkSum, 1024, K2, sm->sres, tid);
    unsigned b3 = sm->sres[0], gt3 = sm->sres[1], K3 = K2 - gt3;
    unsigned ustar = (b1 << 21) | (b2 << 10) | b3;
    int totalGt = (int)(KPRE - K3);         // count strictly > pivot
    __syncthreads();

    // ---- pass D: partition candidates (uniform trips, aggregated appends) ----
    for (int it = 0; it < iters; ++it) {
        int t = (it << 10) + tid;
        bool act = t < C;
        unsigned long long k = act ? cand[t] : 0ull;
        unsigned u = (unsigned)(k >> 32);
        bool isGt = act && (u > ustar);
        int p = wappend(&sm->cntGt, isGt);
        if (isGt) sm->selKey[p] = k;
        bool isEq = act && (u == ustar);
        int p2 = wappend(&sm->cntEq, isEq);
        if (isEq && p2 < 2048) eqIdx[p2] = (int)~((unsigned)(k & 0xFFFFFFFFull));
    }
    __syncthreads();

    // ---- pass E: tie resolution by smallest index (jax top_k semantics) ----
    int E = sm->cntEq; if (E > 2048) E = 2048;
    for (int t = tid; t < E; t += 1024) {
        int my = eqIdx[t], r = 0;
        for (int s = 0; s < E; ++s) r += (eqIdx[s] < my);
        if (r < (int)K3)
            sm->selKey[totalGt + r] = ((unsigned long long)ustar << 32) | (unsigned)(~my);
    }
    __syncthreads();

    // ---- hybrid bitonic sort, descending (smem stages j>=32, shfl j<=16) ----
    unsigned long long key = sm->selKey[tid];
    int cur = 0;
#pragma unroll
    for (int k = 2; k <= 32; k <<= 1) {
        bool desc = ((tid & k) == 0);
#pragma unroll
        for (int j = k >> 1; j > 0; j >>= 1) {
            unsigned long long other = __shfl_xor_sync(0xFFFFFFFFu, key, j);
            bool lower = (tid & j) == 0;
            key = (lower == desc) ? umaxll(key, other) : uminll(key, other);
        }
    }
    __syncthreads();
    for (int k = 64; k <= KPRE; k <<= 1) {
        bool desc = ((tid & k) == 0);
        for (int j = k >> 1; j >= 32; j >>= 1) {
            unsigned long long* B = cur ? sm->sbuf1 : sm->selKey;
            B[tid] = key;
            __syncthreads();
            unsigned long long other = B[tid ^ j];
            bool lower = (tid & j) == 0;
            key = (lower == desc) ? umaxll(key, other) : uminll(key, other);
            cur ^= 1;
        }
#pragma unroll
        for (int j = 16; j > 0; j >>= 1) {
            unsigned long long other = __shfl_xor_sync(0xFFFFFFFFu, key, j);
            bool lower = (tid & j) == 0;
            key = (lower == desc) ? umaxll(key, other) : uminll(key, other);
        }
    }

    // ---- gather boxes / class / score into SMEM (bit-exact arithmetic) ----
    {
        unsigned n = ~((unsigned)(key & 0xFFFFFFFFull));
        unsigned u = (unsigned)(key >> 32);
        unsigned sb = (u & 0x80000000u) ? (u ^ 0x80000000u) : ~u;
        float sc = __int_as_float((int)sb);
        const float* p = pred + ((size_t)b * NANCH + n) * 85;
        float cx = __ldg(p), cy = __ldg(p + 1), w = __ldg(p + 2), h = __ldg(p + 3);
        float hw = __fmul_rn(w, 0.5f), hh = __fmul_rn(h, 0.5f);
        float x1 = __fsub_rn(cx, hw), y1 = __fsub_rn(cy, hh);
        float x2 = __fadd_rn(cx, hw), y2 = __fadd_rn(cy, hh);
        float cf = (float)(int)g_cls[b][n];
        float off = __fmul_rn(cf, 7680.0f);
        float o0 = __fadd_rn(x1, off), o1 = __fadd_rn(y1, off);
        float o2 = __fadd_rn(x2, off), o3 = __fadd_rn(y2, off);
        sm->bx1[tid] = x1; sm->by1[tid] = y1; sm->bx2[tid] = x2; sm->by2[tid] = y2;
        sm->s0[tid] = o0;  sm->s1[tid] = o1;  sm->s2[tid] = o2;  sm->s3[tid] = o3;
        sm->sar[tid] = __fmul_rn(__fsub_rn(o2, o0), __fsub_rn(o3, o1));
        sm->ssc[tid] = sc;
        sm->scf[tid] = cf;
        if (tid == 0) sm->skc = 0;
    }
    int V = __syncthreads_count(sm->ssc[tid] > 0.0f);   // valid == prefix (sorted)

    // ---- lazy mask + greedy scan, 32 rows per chunk, early exit at 100 ----
    unsigned kept = 0;
    int kc = 0;
    for (int c = 0; c < 32; ++c) {
        {
            int i = (c << 5) + warp;
            float a0 = sm->s0[i], a1 = sm->s1[i], a2 = sm->s2[i], a3 = sm->s3[i];
            float aa = sm->sar[i];
            for (int t = 0; t <= c; ++t) {
                int j = (t << 5) + l;
                bool bit = false;
                if (j < i) {
                    float xx1 = fmaxf(a0, sm->s0[j]);
                    float yy1 = fmaxf(a1, sm->s1[j]);
                    float xx2 = fminf(a2, sm->s2[j]);
                    float yy2 = fminf(a3, sm->s3[j]);
                    float ww = fmaxf(__fsub_rn(xx2, xx1), 0.0f);
                    float hh = fmaxf(__fsub_rn(yy2, yy1), 0.0f);
                    float inter = __fmul_rn(ww, hh);
                    float uni = __fsub_rn(__fadd_rn(aa, sm->sar[j]), inter);
                    float iou = __fdiv_rn(inter, __fadd_rn(uni, 1e-7f));
                    bit = iou > 0.45f;
                }
                unsigned word = __ballot_sync(0xFFFFFFFFu, bit);
                if (l == 0) sm->smask[warp][t] = word;
            }
        }
        __syncthreads();

        if (tid < 32) {                     // warp 0: scan this chunk
            unsigned mA[32];
#pragma unroll
            for (int k = 0; k < 32; ++k) mA[k] = (l <= c) ? sm->smask[k][l] : 0u;
            unsigned hv = 0;
#pragma unroll
            for (int k = 0; k < 32; ++k) hv |= ((mA[k] & kept) ? 1u : 0u) << k;
            unsigned grpHit = __reduce_or_sync(0xFFFFFFFFu, hv);
            int add = 0;
            if (l == c) {
                unsigned newBits = 0;
                int kcl = kc;
#pragma unroll
                for (int k = 0; k < 32; ++k) {
                    int i = (c << 5) + k;
                    bool sup = ((grpHit >> k) & 1u) != 0u || (mA[k] & newBits) != 0u;
                    if (i < V && !sup) {
                        newBits |= 1u << k;
                        if (kcl < MAXDET) sm->list[kcl] = i;
                        kcl++; add++;
                    }
                }
                kept |= newBits;
            }
            kc += __shfl_sync(0xFFFFFFFFu, add, c);
            if (l == 0) sm->skc = kc;
        }
        __syncthreads();
        if (sm->skc >= MAXDET) break;       // only first 100 kept observable
        if (((c + 1) << 5) >= V) break;     // remaining rows all invalid
    }

    // ---- output (zeros beyond K; replaces memset) ----
    int K = sm->skc; if (K > MAXDET) K = MAXDET;
    for (int s = tid; s < MAXDET; s += 1024) {
        float v0 = 0.f, v1 = 0.f, v2 = 0.f, v3 = 0.f, v4 = 0.f, v5 = 0.f;
        if (s < K) {
            int i = sm->list[s];
            v0 = sm->bx1[i]; v1 = sm->by1[i]; v2 = sm->bx2[i]; v3 = sm->by2[i];
            v4 = sm->ssc[i]; v5 = sm->scf[i];
        }
        float* o = out + ((size_t)(b * MAXDET + s)) * 6;
        o[0] = v0; o[1] = v1; o[2] = v2; o[3] = v3; o[4] = v4; o[5] = v5;
    }

    // ---- replay-safe barrier reset (after ALL workers passed the spin) ----
    __syncthreads();
    if (tid == 0) {
        __threadfence();
        atomicAdd(&g_wpass, 1u);
        if (b == 0) {
            while (atomicAdd(&g_wpass, 0u) < (unsigned)BATCH) __nanosleep(64);
            atomicExch(&g_arrive, 0u);
            atomicExch(&g_wpass, 0u);
        }
    }
}

// ---------------- launch ------------------------------------------------------
extern "C" void kernel_launch(void* const* d_in, const int* in_sizes, int n_in,
                              void* d_out, int out_size)
{
    const float* pred = (const float*)d_in[0];
    float* out = (float*)d_out;

    static int smem_set = 0;
    if (!smem_set) {
        cudaFuncSetAttribute(k_all, cudaFuncAttributeMaxDynamicSharedMemorySize,
                             (int)sizeof(SmemU));
        smem_set = 1;
    }
    k_all<<<GRID, 1024, sizeof(SmemU)>>>(pred, out);
}

// round 10
// speedup vs baseline: 1.2239x; 1.2239x over previous
#include <cuda_runtime.h>
#include <stdint.h>

#define BATCH  8
#define NANCH  100800
#define KPRE   1024
#define MAXDET 100
#define GRID   148
#define TILEA  192                      // 525 * 192 == 100800
#define NTILES (BATCH * 525)            // 4200
#define N4     (NANCH / 4)              // 25200
#define TILE4  (TILEA * 85 / 4)         // 4080 float4 per tile

// ---------------- scratch (static device memory; no runtime allocation) ------
__device__ unsigned int        g_ukey[BATCH][NANCH];
__device__ unsigned char       g_cls [BATCH][NANCH];
__device__ unsigned int        g_hist[BATCH][2048];     // self-zeroing each run
__device__ unsigned long long  g_cand[BATCH][NANCH];    // pivot-bin candidates
__device__ unsigned int        g_arrive;                // grid barrier (self-reset)
__device__ unsigned int        g_wpass;                 // worker completion count

// ---------------- shared memory union ----------------------------------------
struct SmemB {
    unsigned hist[2048];
    unsigned long long selKey[KPRE];    // sort buffer 0
    unsigned long long sbuf1[KPRE];     // eqIdx storage + sort buffer 1
    float s0[KPRE], s1[KPRE], s2[KPRE], s3[KPRE], sar[KPRE];  // offset boxes
    float bx1[KPRE], by1[KPRE], bx2[KPRE], by2[KPRE];         // raw boxes
    float ssc[KPRE], scf[KPRE];
    unsigned smask[32][32];             // lazy mask chunk: 32 rows x 32 words
    unsigned chunkSum[64];
    unsigned sres[2];
    int list[MAXDET];
    int cntGt, cntEq, cntCand, skc;
};
union SmemU {
    SmemB nms;
    float tile[2][TILEA * 85];          // double-buffered phase-1 tiles (130560 B)
};

// ---------------- helpers -----------------------------------------------------
__device__ __forceinline__ int wappend(int* ctr, bool p)
{
    unsigned m = __ballot_sync(0xFFFFFFFFu, p);
    int pos = -1;
    if (p) {
        int l = threadIdx.x & 31;
        int leader = __ffs(m) - 1;
        int base = 0;
        if (l == leader) base = atomicAdd(ctr, __popc(m));
        base = __shfl_sync(m, base, leader);
        pos = base + __popc(m & ((1u << l) - 1));
    }
    return pos;
}

__device__ __forceinline__ void hist_add(unsigned* hist, unsigned bin, bool q)
{
    unsigned qm = __ballot_sync(0xFFFFFFFFu, q);
    if (q) {
        unsigned peers = __match_any_sync(qm, bin);
        int ld = __ffs(peers) - 1;
        if ((int)(threadIdx.x & 31) == ld) atomicAdd(&hist[bin], (unsigned)__popc(peers));
    }
}

__device__ __forceinline__ void find_bin(unsigned* hist, unsigned* chunkSum,
                                         int NB, unsigned K, unsigned* sres, int tid)
{
    int nch = NB >> 5;
    if (tid < nch) {
        unsigned s = 0;
        int base = tid << 5;
#pragma unroll 8
        for (int i = 0; i < 32; ++i) s += hist[base + i];
        chunkSum[tid] = s;
    }
    __syncthreads();
    if (tid == 0) {
        unsigned acc = 0;
        int c = nch - 1;
        for (;; --c) {
            unsigned cs = chunkSum[c];
            if (acc + cs >= K) break;
            acc += cs;
        }
        int bin = (c << 5) + 31;
        for (;; --bin) {
            unsigned hv = hist[bin];
            if (acc + hv >= K) break;
            acc += hv;
        }
        sres[0] = (unsigned)bin;
        sres[1] = acc;          // count strictly above bin
    }
    __syncthreads();
}

__device__ __forceinline__ unsigned long long umaxll(unsigned long long a, unsigned long long b)
{ return a > b ? a : b; }
__device__ __forceinline__ unsigned long long uminll(unsigned long long a, unsigned long long b)
{ return a < b ? a : b; }

// ---------------- the single fused kernel -------------------------------------
__global__ void __launch_bounds__(1024, 1) k_all(const float* __restrict__ pred,
                                                 float* __restrict__ out)
{
    extern __shared__ unsigned char dyn[];
    SmemU* smu = (SmemU*)dyn;

    int tid = threadIdx.x;
    int l = tid & 31, warp = tid >> 5;

    // ============ PHASE 1: score / argmax / key / histogram (all CTAs) =======
    // Double-buffered: prefetch tile T+GRID into registers while computing T.
    {
        int parity = 0;
        float4 r[4];
        {   // prefetch first tile
            int b0 = blockIdx.x / 525, a0 = (blockIdx.x % 525) * TILEA;
            const float4* p4 = (const float4*)(pred + ((size_t)b0 * NANCH + a0) * 85);
#pragma unroll
            for (int k = 0; k < 4; ++k) {
                int idx = k * 1024 + tid;
                r[k] = (idx < TILE4) ? p4[idx] : make_float4(0.f, 0.f, 0.f, 0.f);
            }
        }
        for (int T = blockIdx.x; T < NTILES; T += GRID) {
            float4* t4 = (float4*)smu->tile[parity];
#pragma unroll
            for (int k = 0; k < 4; ++k) {
                int idx = k * 1024 + tid;
                if (idx < TILE4) t4[idx] = r[k];
            }
            int Tn = T + GRID;                      // prefetch next tile
            if (Tn < NTILES) {
                int bn = Tn / 525, an = (Tn % 525) * TILEA;
                const float4* p4 = (const float4*)(pred + ((size_t)bn * NANCH + an) * 85);
#pragma unroll
                for (int k = 0; k < 4; ++k) {
                    int idx = k * 1024 + tid;
                    if (idx < TILE4) r[k] = p4[idx];
                }
            }
            __syncthreads();                        // tile[parity] ready

            int b = T / 525;
            int astart = (T % 525) * TILEA;
            const float* smf = smu->tile[parity];
            if (warp < 24) {                        // 768 thr: 4 per anchor
                int a = tid >> 2, ch = tid & 3;
                const float* row = smf + a * 85;
                float obj = row[4];
                float v = __fmul_rn(row[5 + ch], obj);
                int bi = ch;
#pragma unroll
                for (int c = ch + 4; c < 80; c += 4) {
                    float x = __fmul_rn(row[5 + c], obj);
                    if (x > v) { v = x; bi = c; }   // strict > == first in chain
                }
                // merge 4-lane group by (value, then lower index) == ref argmax
#pragma unroll
                for (int off = 1; off < 4; off <<= 1) {
                    float ov = __shfl_xor_sync(0xFFFFFFFFu, v, off);
                    int   oi = __shfl_xor_sync(0xFFFFFFFFu, bi, off);
                    if (ov > v || (ov == v && oi < bi)) { v = ov; bi = oi; }
                }
                unsigned u = 0;
                if (ch == 0) {
                    bool  valid = (obj > 0.25f) && (v > 0.25f);
                    float smv = valid ? v : -1.0f;
                    int   sb = __float_as_int(smv);
                    u = (unsigned)sb ^ ((sb < 0) ? 0xFFFFFFFFu : 0x80000000u);
                    int n = astart + a;
                    g_ukey[b][n] = u;
                    g_cls [b][n] = (unsigned char)bi;
                }
                hist_add(&g_hist[b][0], u >> 21, ch == 0);   // warp-aggregated
            }
            parity ^= 1;                            // single barrier per tile is
        }                                           // safe with double buffering
    }

    // ============ grid barrier (all 148 CTAs resident by construction) =======
    __syncthreads();
    if (tid == 0) { __threadfence(); atomicAdd(&g_arrive, 1u); }
    if (blockIdx.x >= BATCH) return;        // non-workers done
    if (tid == 0) {
        while (atomicAdd(&g_arrive, 0u) < (unsigned)GRID) __nanosleep(64);
        __threadfence();
    }
    __syncthreads();

    // ============ PHASE 2: select + sort + gather + lazy-mask NMS ============
    SmemB* sm = &smu->nms;
    int b = blockIdx.x;
    const uint4* uk4 = (const uint4*)&g_ukey[b][0];
    unsigned long long* cand = &g_cand[b][0];
    int* eqIdx = (int*)sm->sbuf1;

    // ---- pass A: histogram from phase 1 (load + self-zero for next run) ----
    sm->hist[tid] = g_hist[b][tid];
    sm->hist[tid + 1024] = g_hist[b][tid + 1024];
    __syncthreads();
    g_hist[b][tid] = 0; g_hist[b][tid + 1024] = 0;
    find_bin(sm->hist, sm->chunkSum, 2048, KPRE, sm->sres, tid);
    unsigned b1 = sm->sres[0], gt1 = sm->sres[1], K1 = KPRE - gt1;
    int C = (int)sm->hist[b1];
    if (tid == 0) { sm->cntGt = 0; sm->cntEq = 0; sm->cntCand = 0; }
    __syncthreads();

    // ---- single key scan: compact sure-winners + pivot-bin candidates ----
    for (int it = 0; it < 25; ++it) {       // uniform trips (warp-sync safe)
        int t = (it << 10) + tid;
        bool act = t < N4;
        uint4 q = act ? uk4[t] : make_uint4(0u, 0u, 0u, 0u);
        unsigned uu[4] = {q.x, q.y, q.z, q.w};
#pragma unroll
        for (int j = 0; j < 4; ++j) {
            unsigned u = uu[j];
            unsigned hb = u >> 21;
            int n = 4 * t + j;
            unsigned long long key = ((unsigned long long)u << 32) | (unsigned)(~n);
            bool isGt = act && (hb > b1);
            int p = wappend(&sm->cntGt, isGt);
            if (isGt) sm->selKey[p] = key;
            bool isEq = act && (hb == b1);
            int p2 = wappend(&sm->cntCand, isEq);
            if (isEq) cand[p2] = key;
        }
    }
    __syncthreads();

    // ---- pass B: mid 11 bits over candidates only ----
    sm->hist[tid] = 0; sm->hist[tid + 1024] = 0;
    __syncthreads();
    int iters = (C + 1023) >> 10;           // uniform across ALL threads
    for (int it = 0; it < iters; ++it) {
        int t = (it << 10) + tid;
        bool act = t < C;
        unsigned long long k = act ? cand[t] : 0ull;
        unsigned u = (unsigned)(k >> 32);
        hist_add(sm->hist, (u >> 10) & 2047u, act);
    }
    __syncthreads();
    find_bin(sm->hist, sm->chunkSum, 2048, K1, sm->sres, tid);
    unsigned b2 = sm->sres[0], gt2 = sm->sres[1], K2 = K1 - gt2;
    __syncthreads();

    // ---- pass C: low 10 bits over candidates matching b2 ----
    sm->hist[tid] = 0;
    __syncthreads();
    for (int it = 0; it < iters; ++it) {
        int t = (it << 10) + tid;
        bool act = t < C;
        unsigned long long k = act ? cand[t] : 0ull;
        unsigned u = (unsigned)(k >> 32);
        hist_add(sm->hist, u & 1023u, act && (((u >> 10) & 2047u) == b2));
    }
    __syncthreads();
    find_bin(sm->hist, sm->chunkSum, 1024, K2, sm->sres, tid);
    unsigned b3 = sm->sres[0], gt3 = sm->sres[1], K3 = K2 - gt3;
    unsigned ustar = (b1 << 21) | (b2 << 10) | b3;
    int totalGt = (int)(KPRE - K3);         // count strictly > pivot
    __syncthreads();

    // ---- pass D: partition candidates (uniform trips, aggregated appends) ----
    for (int it = 0; it < iters; ++it) {
        int t = (it << 10) + tid;
        bool act = t < C;
        unsigned long long k = act ? cand[t] : 0ull;
        unsigned u = (unsigned)(k >> 32);
        bool isGt = act && (u > ustar);
        int p = wappend(&sm->cntGt, isGt);
        if (isGt) sm->selKey[p] = k;
        bool isEq = act && (u == ustar);
        int p2 = wappend(&sm->cntEq, isEq);
        if (isEq && p2 < 2048) eqIdx[p2] = (int)~((unsigned)(k & 0xFFFFFFFFull));
    }
    __syncthreads();

    // ---- pass E: tie resolution by smallest index (jax top_k semantics) ----
    int E = sm->cntEq; if (E > 2048) E = 2048;
    for (int t = tid; t < E; t += 1024) {
        int my = eqIdx[t], r = 0;
        for (int s = 0; s < E; ++s) r += (eqIdx[s] < my);
        if (r < (int)K3)
            sm->selKey[totalGt + r] = ((unsigned long long)ustar << 32) | (unsigned)(~my);
    }
    __syncthreads();

    // ---- hybrid bitonic sort, descending (smem stages j>=32, shfl j<=16) ----
    unsigned long long key = sm->selKey[tid];
    int cur = 0;
#pragma unroll
    for (int k = 2; k <= 32; k <<= 1) {
        bool desc = ((tid & k) == 0);
#pragma unroll
        for (int j = k >> 1; j > 0; j >>= 1) {
            unsigned long long other = __shfl_xor_sync(0xFFFFFFFFu, key, j);
            bool lower = (tid & j) == 0;
            key = (lower == desc) ? umaxll(key, other) : uminll(key, other);
        }
    }
    __syncthreads();
    for (int k = 64; k <= KPRE; k <<= 1) {
        bool desc = ((tid & k) == 0);
        for (int j = k >> 1; j >= 32; j >>= 1) {
            unsigned long long* B = cur ? sm->sbuf1 : sm->selKey;
            B[tid] = key;
            __syncthreads();
            unsigned long long other = B[tid ^ j];
            bool lower = (tid & j) == 0;
            key = (lower == desc) ? umaxll(key, other) : uminll(key, other);
            cur ^= 1;
        }
#pragma unroll
        for (int j = 16; j > 0; j >>= 1) {
            unsigned long long other = __shfl_xor_sync(0xFFFFFFFFu, key, j);
            bool lower = (tid & j) == 0;
            key = (lower == desc) ? umaxll(key, other) : uminll(key, other);
        }
    }

    // ---- gather boxes / class / score into SMEM (bit-exact arithmetic) ----
    {
        unsigned n = ~((unsigned)(key & 0xFFFFFFFFull));
        unsigned u = (unsigned)(key >> 32);
        unsigned sb = (u & 0x80000000u) ? (u ^ 0x80000000u) : ~u;
        float sc = __int_as_float((int)sb);
        const float* p = pred + ((size_t)b * NANCH + n) * 85;
        float cx = __ldg(p), cy = __ldg(p + 1), w = __ldg(p + 2), h = __ldg(p + 3);
        float hw = __fmul_rn(w, 0.5f), hh = __fmul_rn(h, 0.5f);
        float x1 = __fsub_rn(cx, hw), y1 = __fsub_rn(cy, hh);
        float x2 = __fadd_rn(cx, hw), y2 = __fadd_rn(cy, hh);
        float cf = (float)(int)g_cls[b][n];
        float off = __fmul_rn(cf, 7680.0f);
        float o0 = __fadd_rn(x1, off), o1 = __fadd_rn(y1, off);
        float o2 = __fadd_rn(x2, off), o3 = __fadd_rn(y2, off);
        sm->bx1[tid] = x1; sm->by1[tid] = y1; sm->bx2[tid] = x2; sm->by2[tid] = y2;
        sm->s0[tid] = o0;  sm->s1[tid] = o1;  sm->s2[tid] = o2;  sm->s3[tid] = o3;
        sm->sar[tid] = __fmul_rn(__fsub_rn(o2, o0), __fsub_rn(o3, o1));
        sm->ssc[tid] = sc;
        sm->scf[tid] = cf;
        if (tid == 0) sm->skc = 0;
    }
    int V = __syncthreads_count(sm->ssc[tid] > 0.0f);   // valid == prefix (sorted)

    // ---- lazy mask + greedy scan, 32 rows per chunk, early exit at 100 ----
    unsigned kept = 0;
    int kc = 0;
    for (int c = 0; c < 32; ++c) {
        {
            int i = (c << 5) + warp;
            float a0 = sm->s0[i], a1 = sm->s1[i], a2 = sm->s2[i], a3 = sm->s3[i];
            float aa = sm->sar[i];
            for (int t = 0; t <= c; ++t) {
                int j = (t << 5) + l;
                bool bit = false;
                if (j < i) {
                    float xx1 = fmaxf(a0, sm->s0[j]);
                    float yy1 = fmaxf(a1, sm->s1[j]);
                    float xx2 = fminf(a2, sm->s2[j]);
                    float yy2 = fminf(a3, sm->s3[j]);
                    float ww = fmaxf(__fsub_rn(xx2, xx1), 0.0f);
                    float hh = fmaxf(__fsub_rn(yy2, yy1), 0.0f);
                    float inter = __fmul_rn(ww, hh);
                    float uni = __fsub_rn(__fadd_rn(aa, sm->sar[j]), inter);
                    float iou = __fdiv_rn(inter, __fadd_rn(uni, 1e-7f));
                    bit = iou > 0.45f;
                }
                unsigned word = __ballot_sync(0xFFFFFFFFu, bit);
                if (l == 0) sm->smask[warp][t] = word;
            }
        }
        __syncthreads();

        if (tid < 32) {                     // warp 0: scan this chunk
            unsigned mA[32];
#pragma unroll
            for (int k = 0; k < 32; ++k) mA[k] = (l <= c) ? sm->smask[k][l] : 0u;
            unsigned hv = 0;
#pragma unroll
            for (int k = 0; k < 32; ++k) hv |= ((mA[k] & kept) ? 1u : 0u) << k;
            unsigned grpHit = __reduce_or_sync(0xFFFFFFFFu, hv);
            int add = 0;
            if (l == c) {
                unsigned newBits = 0;
                int kcl = kc;
#pragma unroll
                for (int k = 0; k < 32; ++k) {
                    int i = (c << 5) + k;
                    bool sup = ((grpHit >> k) & 1u) != 0u || (mA[k] & newBits) != 0u;
                    if (i < V && !sup) {
                        newBits |= 1u << k;
                        if (kcl < MAXDET) sm->list[kcl] = i;
                        kcl++; add++;
                    }
                }
                kept |= newBits;
            }
            kc += __shfl_sync(0xFFFFFFFFu, add, c);
            if (l == 0) sm->skc = kc;
        }
        __syncthreads();
        if (sm->skc >= MAXDET) break;       // only first 100 kept observable
        if (((c + 1) << 5) >= V) break;     // remaining rows all invalid
    }

    // ---- output (zeros beyond K; replaces memset) ----
    int K = sm->skc; if (K > MAXDET) K = MAXDET;
    for (int s = tid; s < MAXDET; s += 1024) {
        float v0 = 0.f, v1 = 0.f, v2 = 0.f, v3 = 0.f, v4 = 0.f, v5 = 0.f;
        if (s < K) {
            int i = sm->list[s];
            v0 = sm->bx1[i]; v1 = sm->by1[i]; v2 = sm->bx2[i]; v3 = sm->by2[i];
            v4 = sm->ssc[i]; v5 = sm->scf[i];
        }
        float* o = out + ((size_t)(b * MAXDET + s)) * 6;
        o[0] = v0; o[1] = v1; o[2] = v2; o[3] = v3; o[4] = v4; o[5] = v5;
    }

    // ---- replay-safe barrier reset (after ALL workers passed the spin) ----
    __syncthreads();
    if (tid == 0) {
        __threadfence();
        atomicAdd(&g_wpass, 1u);
        if (b == 0) {
            while (atomicAdd(&g_wpass, 0u) < (unsigned)BATCH) __nanosleep(64);
            atomicExch(&g_arrive, 0u);
            atomicExch(&g_wpass, 0u);
        }
    }
}

// ---------------- launch ------------------------------------------------------
extern "C" void kernel_launch(void* const* d_in, const int* in_sizes, int n_in,
                              void* d_out, int out_size)
{
    const float* pred = (const float*)d_in[0];
    float* out = (float*)d_out;

    static int smem_set = 0;
    if (!smem_set) {
        cudaFuncSetAttribute(k_all, cudaFuncAttributeMaxDynamicSharedMemorySize,
                             (int)sizeof(SmemU));
        smem_set = 1;
    }
    k_all<<<GRID, 1024, sizeof(SmemU)>>>(pred, out);
}

// round 12
// speedup vs baseline: 1.5758x; 1.2875x over previous
#include <cuda_runtime.h>
#include <stdint.h>

#define BATCH  8
#define NANCH  100800
#define KPRE   1024
#define MAXDET 100
#define N4     (NANCH / 4)              // 25200

typedef unsigned long long ull;

// ---------------- scratch (static device memory; no runtime allocation) ------
__device__ unsigned int  g_ukey  [BATCH][NANCH];
__device__ unsigned char g_cls   [BATCH][NANCH];
__device__ unsigned int  g_hist16[BATCH][65536];   // 16-bit-bin hist (self-zero)
__device__ unsigned int  g_chunk [BATCH][1024];    // 64-bin chunk hist (self-zero)

// ---------------- kernel 1: coalesced score / argmax / key / histograms ------
__device__ __forceinline__ void gadd(unsigned* dst, unsigned bin, bool q)
{
    unsigned qm = __ballot_sync(0xFFFFFFFFu, q);
    if (q) {
        unsigned peers = __match_any_sync(qm, bin);
        int ld = __ffs(peers) - 1;
        if ((int)(threadIdx.x & 31) == ld) atomicAdd(&dst[bin], (unsigned)__popc(peers));
    }
}

__global__ void __launch_bounds__(96) k_score(const float* __restrict__ pred)
{
    __shared__ float tile[3][2720];        // 3 warps x 32 anchors x 85 floats

    int b = blockIdx.y;
    int w = threadIdx.x >> 5, l = threadIdx.x & 31;

    int base = blockIdx.x * 96 + w * 32;                 // 1050*96 == 100800 exactly
    const float4* p4 = (const float4*)(pred + ((size_t)b * NANCH + base) * 85);
    float4* t4 = (float4*)tile[w];
#pragma unroll
    for (int k = 0; k < 21; ++k) t4[k * 32 + l] = p4[k * 32 + l];
    if (l < 8) t4[672 + l] = p4[672 + l];                // 680 float4 = 2720 floats
    __syncwarp();                                        // per-warp tile, warp-local

    const float* row = &tile[w][l * 85];                 // stride 85: conflict-free
    float obj = row[4];

    // 4 independent strict-> chains merged by (value, lower index) ==
    // min-index-of-max == reference first-occurrence argmax
    float v0 = __fmul_rn(row[5], obj);     int i0 = 0;
    float v1 = __fmul_rn(row[6], obj);     int i1 = 1;
    float v2 = __fmul_rn(row[7], obj);     int i2 = 2;
    float v3 = __fmul_rn(row[8], obj);     int i3 = 3;
#pragma unroll
    for (int t = 1; t < 20; ++t) {
        int c = 4 * t;
        float a  = __fmul_rn(row[5 + c], obj);
        float bq = __fmul_rn(row[6 + c], obj);
        float cq = __fmul_rn(row[7 + c], obj);
        float dq = __fmul_rn(row[8 + c], obj);
        if (a  > v0) { v0 = a;  i0 = c;     }
        if (bq > v1) { v1 = bq; i1 = c + 1; }
        if (cq > v2) { v2 = cq; i2 = c + 2; }
        if (dq > v3) { v3 = dq; i3 = c + 3; }
    }
    float best = v0; int bi = i0;
    if (v1 > best || (v1 == best && i1 < bi)) { best = v1; bi = i1; }
    if (v2 > best || (v2 == best && i2 < bi)) { best = v2; bi = i2; }
    if (v3 > best || (v3 == best && i3 < bi)) { best = v3; bi = i3; }

    bool  valid = (obj > 0.25f) && (best > 0.25f);
    float sm    = valid ? best : -1.0f;
    int   sb    = __float_as_int(sm);
    unsigned u  = (unsigned)sb ^ ((sb < 0) ? 0xFFFFFFFFu : 0x80000000u);
    int n = base + l;
    g_ukey[b][n] = u;
    g_cls [b][n] = (unsigned char)bi;

    gadd(&g_hist16[b][0], u >> 16, true);    // fine bins (65536)
    gadd(&g_chunk [b][0], u >> 22, true);    // chunk bins (1024, 64 fine each)
}

// ---------------- kernel 2: select + sort + gather + lazy-mask NMS -----------
struct SmemB {
    ull sel[2048];                      // selected keys; sort buffer 0 (A|B)
    ull sb2[2048];                      // sort buffer 1
    float s0[KPRE], s1[KPRE], s2[KPRE], s3[KPRE], sar[KPRE];  // offset boxes
    float bx1[KPRE], by1[KPRE], bx2[KPRE], by2[KPRE];         // raw boxes
    float ssc[KPRE], scf[KPRE];
    unsigned cs[1024];                  // chunk counts
    unsigned ss[32];                    // super-chunk (32-chunk) sums
    unsigned binv[64];                  // fine bins of winning chunk
    unsigned smask[32][32];             // lazy mask chunk: 32 rows x 32 words
    unsigned sres[2];
    int list[MAXDET];
    int cnt, skc;
};

__device__ __forceinline__ ull umaxll(ull a, ull b) { return a > b ? a : b; }
__device__ __forceinline__ ull uminll(ull a, ull b) { return a < b ? a : b; }

__global__ void __launch_bounds__(1024) k_nms(const float* __restrict__ pred,
                                              float* __restrict__ out)
{
    extern __shared__ unsigned char dyn[];
    SmemB* sm = (SmemB*)dyn;

    int b = blockIdx.x, tid = threadIdx.x;
    int l = tid & 31, warp = tid >> 5;
    const uint4* uk4 = (const uint4*)&g_ukey[b][0];

    // ---- find 16-bit threshold bin b1 (count above < 1024 <= count >= b1) ----
    unsigned myc = g_chunk[b][tid];
    g_chunk[b][tid] = 0;                               // self-zero for next run
    sm->cs[tid] = myc;
    unsigned v = myc;
#pragma unroll
    for (int o = 16; o; o >>= 1) v += __shfl_xor_sync(0xFFFFFFFFu, v, o);
    if (l == 0) sm->ss[warp] = v;
    if (tid == 0) { sm->cnt = 0; sm->skc = 0; }
    __syncthreads();
    if (tid == 0) {
        unsigned acc = 0;
        int S = 31;
        for (;; --S) { unsigned x = sm->ss[S]; if (acc + x >= KPRE) break; acc += x; }
        int c = (S << 5) + 31;
        for (;; --c) { unsigned x = sm->cs[c]; if (acc + x >= KPRE) break; acc += x; }
        sm->sres[0] = (unsigned)c;
        sm->sres[1] = acc;
    }
    __syncthreads();
    int ch = (int)sm->sres[0];
    unsigned acc0 = sm->sres[1];
    if (tid < 64) sm->binv[tid] = g_hist16[b][(ch << 6) + tid];
    __syncthreads();
    if (tid == 0) {
        unsigned acc = acc0;
        int bin = 63;
        for (;; --bin) { unsigned x = sm->binv[bin]; if (acc + x >= KPRE) break; acc += x; }
        sm->sres[0] = (unsigned)((ch << 6) + bin);
    }
    // self-zero fine hist (binv already captured)
    for (int i = tid; i < 65536; i += 1024) g_hist16[b][i] = 0;
    __syncthreads();
    unsigned b1 = sm->sres[0];

    // ---- single scan: append ALL keys with fine-bin >= b1 (order-free) ----
    for (int it = 0; it < 25; ++it) {                  // uniform trips
        int t = (it << 10) + tid;
        bool act = t < N4;
        uint4 q = act ? uk4[t] : make_uint4(0u, 0u, 0u, 0u);
        unsigned uu[4] = {q.x, q.y, q.z, q.w};
        bool h[4];
        int c = 0;
#pragma unroll
        for (int j = 0; j < 4; ++j) { h[j] = act && ((uu[j] >> 16) >= b1); c += h[j]; }
        int pre = c;
#pragma unroll
        for (int o = 1; o < 32; o <<= 1) {
            int y = __shfl_up_sync(0xFFFFFFFFu, pre, o);
            if (l >= o) pre += y;
        }
        int tot = __shfl_sync(0xFFFFFFFFu, pre, 31);
        if (tot > 0) {
            int base2 = 0;
            if (l == 31) base2 = atomicAdd(&sm->cnt, tot);
            base2 = __shfl_sync(0xFFFFFFFFu, base2, 31);
            int p = base2 + pre - c;
#pragma unroll
            for (int j = 0; j < 4; ++j)
                if (h[j]) {
                    if (p < 2048)
                        sm->sel[p] = ((ull)uu[j] << 32) | (unsigned)(~(4 * t + j));
                    p++;
                }
        }
    }
    __syncthreads();
    int total = sm->cnt; if (total > 2048) total = 2048;
    for (int i = tid; i < 2048; i += 1024)
        if (i >= total) sm->sel[i] = 0;                // pads sort to the bottom
    __syncthreads();

    // ---- bitonic sort of 2048 keys, descending (value, then smaller index) --
    // 2 keys per thread: A at pos tid, B at pos tid+1024. Hybrid shfl/smem.
    ull kA = sm->sel[tid], kB = sm->sel[tid + 1024];
    int cur = 0;
    for (int k = 2; k <= 1024; k <<= 1) {
        bool dA = ((tid & k) == 0);
        bool dB = (((tid + 1024) & k) == 0);           // differs only at k=1024
        for (int j = k >> 1; j >= 32; j >>= 1) {
            ull* B = cur ? sm->sb2 : sm->sel;
            B[tid] = kA; B[tid + 1024] = kB;
            __syncthreads();
            ull oA = B[tid ^ j], oB = B[(tid ^ j) + 1024];
            bool lower = (tid & j) == 0;
            kA = (lower == dA) ? umaxll(kA, oA) : uminll(kA, oA);
            kB = (lower == dB) ? umaxll(kB, oB) : uminll(kB, oB);
            cur ^= 1;
        }
        int j0 = (k >> 1) < 16 ? (k >> 1) : 16;
        for (int j = j0; j >= 1; j >>= 1) {
            ull oA = __shfl_xor_sync(0xFFFFFFFFu, kA, j);
            ull oB = __shfl_xor_sync(0xFFFFFFFFu, kB, j);
            bool lower = (tid & j) == 0;
            kA = (lower == dA) ? umaxll(kA, oA) : uminll(kA, oA);
            kB = (lower == dB) ? umaxll(kB, oB) : uminll(kB, oB);
        }
    }
    {   // final stage k=2048: descending everywhere
        ull hi = umaxll(kA, kB), lo = uminll(kA, kB);  // j=1024: in-thread pair
        kA = hi; kB = lo;
        for (int j = 512; j >= 32; j >>= 1) {
            ull* B = cur ? sm->sb2 : sm->sel;
            B[tid] = kA; B[tid + 1024] = kB;
            __syncthreads();
            ull oA = B[tid ^ j], oB = B[(tid ^ j) + 1024];
            bool lower = (tid & j) == 0;
            kA = lower ? umaxll(kA, oA) : uminll(kA, oA);
            kB = lower ? umaxll(kB, oB) : uminll(kB, oB);
            cur ^= 1;
        }
#pragma unroll
        for (int j = 16; j >= 1; j >>= 1) {
            ull oA = __shfl_xor_sync(0xFFFFFFFFu, kA, j);
            ull oB = __shfl_xor_sync(0xFFFFFFFFu, kB, j);
            bool lower = (tid & j) == 0;
            kA = lower ? umaxll(kA, oA) : uminll(kA, oA);
            kB = lower ? umaxll(kB, oB) : uminll(kB, oB);
        }
    }
    // kA now holds rank-tid key (descending) == reference top_k order

    // ---- gather boxes / class / score into SMEM (bit-exact arithmetic) ----
    {
        unsigned n = ~((unsigned)(kA & 0xFFFFFFFFull));
        unsigned u = (unsigned)(kA >> 32);
        unsigned sb = (u & 0x80000000u) ? (u ^ 0x80000000u) : ~u;
        float sc = __int_as_float((int)sb);
        const float* p = pred + ((size_t)b * NANCH + n) * 85;
        float cx = __ldg(p), cy = __ldg(p + 1), w = __ldg(p + 2), h = __ldg(p + 3);
        float hw = __fmul_rn(w, 0.5f), hh = __fmul_rn(h, 0.5f);
        float x1 = __fsub_rn(cx, hw), y1 = __fsub_rn(cy, hh);
        float x2 = __fadd_rn(cx, hw), y2 = __fadd_rn(cy, hh);
        float cf = (float)(int)g_cls[b][n];
        float off = __fmul_rn(cf, 7680.0f);
        float o0 = __fadd_rn(x1, off), o1 = __fadd_rn(y1, off);
        float o2 = __fadd_rn(x2, off), o3 = __fadd_rn(y2, off);
        sm->bx1[tid] = x1; sm->by1[tid] = y1; sm->bx2[tid] = x2; sm->by2[tid] = y2;
        sm->s0[tid] = o0;  sm->s1[tid] = o1;  sm->s2[tid] = o2;  sm->s3[tid] = o3;
        sm->sar[tid] = __fmul_rn(__fsub_rn(o2, o0), __fsub_rn(o3, o1));
        sm->ssc[tid] = sc;
        sm->scf[tid] = cf;
    }
    int V = __syncthreads_count(sm->ssc[tid] > 0.0f);  // valid == prefix (sorted)

    // ---- lazy mask + greedy scan, 32 rows per chunk, early exit at 100 ----
    unsigned kept = 0;
    int kc = 0;
    for (int c = 0; c < 32; ++c) {
        {
            int i = (c << 5) + warp;
            float a0 = sm->s0[i], a1 = sm->s1[i], a2 = sm->s2[i], a3 = sm->s3[i];
            float aa = sm->sar[i];
            for (int t = 0; t <= c; ++t) {
                int j = (t << 5) + l;
                bool bit = false;
                if (j < i) {
                    float xx1 = fmaxf(a0, sm->s0[j]);
                    float yy1 = fmaxf(a1, sm->s1[j]);
                    float xx2 = fminf(a2, sm->s2[j]);
                    float yy2 = fminf(a3, sm->s3[j]);
                    float ww = fmaxf(__fsub_rn(xx2, xx1), 0.0f);
                    float hh = fmaxf(__fsub_rn(yy2, yy1), 0.0f);
                    float inter = __fmul_rn(ww, hh);
                    float uni = __fsub_rn(__fadd_rn(aa, sm->sar[j]), inter);
                    float iou = __fdiv_rn(inter, __fadd_rn(uni, 1e-7f));
                    bit = iou > 0.45f;
                }
                unsigned word = __ballot_sync(0xFFFFFFFFu, bit);
                if (l == 0) sm->smask[warp][t] = word;
            }
        }
        __syncthreads();

        if (tid < 32) {                     // warp 0: scan this chunk
            unsigned mA[32];
#pragma unroll
            for (int k = 0; k < 32; ++k) mA[k] = (l <= c) ? sm->smask[k][l] : 0u;
            unsigned hv = 0;
#pragma unroll
            for (int k = 0; k < 32; ++k) hv |= ((mA[k] & kept) ? 1u : 0u) << k;
            unsigned grpHit = __reduce_or_sync(0xFFFFFFFFu, hv);
            int add = 0;
            if (l == c) {
                unsigned newBits = 0;
                int kcl = kc;
#pragma unroll
                for (int k = 0; k < 32; ++k) {
                    int i = (c << 5) + k;
                    bool sup = ((grpHit >> k) & 1u) != 0u || (mA[k] & newBits) != 0u;
                    if (i < V && !sup) {
                        newBits |= 1u << k;
                        if (kcl < MAXDET) sm->list[kcl] = i;
                        kcl++; add++;
                    }
                }
                kept |= newBits;
            }
            kc += __shfl_sync(0xFFFFFFFFu, add, c);
            if (l == 0) sm->skc = kc;
        }
        __syncthreads();
        if (sm->skc >= MAXDET) break;       // only first 100 kept observable
        if (((c + 1) << 5) >= V) break;     // remaining rows all invalid
    }

    // ---- output (zeros beyond K; replaces memset) ----
    int K = sm->skc; if (K > MAXDET) K = MAXDET;
    for (int s = tid; s < MAXDET; s += 1024) {
        float v0 = 0.f, v1 = 0.f, v2 = 0.f, v3 = 0.f, v4 = 0.f, v5 = 0.f;
        if (s < K) {
            int i = sm->list[s];
            v0 = sm->bx1[i]; v1 = sm->by1[i]; v2 = sm->bx2[i]; v3 = sm->by2[i];
            v4 = sm->ssc[i]; v5 = sm->scf[i];
        }
        float* o = out + ((size_t)(b * MAXDET + s)) * 6;
        o[0] = v0; o[1] = v1; o[2] = v2; o[3] = v3; o[4] = v4; o[5] = v5;
    }
}

// ---------------- launch ------------------------------------------------------
extern "C" void kernel_launch(void* const* d_in, const int* in_sizes, int n_in,
                              void* d_out, int out_size)
{
    const float* pred = (const float*)d_in[0];
    float* out = (float*)d_out;

    static int smem_set = 0;
    if (!smem_set) {
        cudaFuncSetAttribute(k_nms, cudaFuncAttributeMaxDynamicSharedMemorySize,
                             (int)sizeof(SmemB));
        smem_set = 1;
    }
    k_score<<<dim3(1050, BATCH), 96>>>(pred);
    k_nms  <<<BATCH, 1024, sizeof(SmemB)>>>(pred, out);
}

// round 13
// speedup vs baseline: 1.6555x; 1.0506x over previous
#include <cuda_runtime.h>
#include <stdint.h>

#define BATCH  8
#define NANCH  100800
#define KPRE   1024
#define MAXDET 100
#define N4     (NANCH / 4)              // 25200
#define HBASE  0xBE80u                  // bin of smallest possible valid score (>0.25)
#define HBINS  512                      // window covers score (0.25, ~4); top bin = catch-all

typedef unsigned long long ull;

// ---------------- scratch (static device memory; no runtime allocation) ------
__device__ unsigned int  g_ukey [BATCH][NANCH];
__device__ unsigned char g_cls  [BATCH][NANCH];
__device__ unsigned int  g_histS[BATCH][HBINS];    // windowed 16-bit hist (self-zero)

// ---------------- kernel 1: coalesced score / argmax / key / histogram -------
__device__ __forceinline__ void gadd(unsigned* dst, unsigned bin, bool q)
{
    unsigned qm = __ballot_sync(0xFFFFFFFFu, q);
    if (q) {
        unsigned peers = __match_any_sync(qm, bin);
        int ld = __ffs(peers) - 1;
        if ((int)(threadIdx.x & 31) == ld) atomicAdd(&dst[bin], (unsigned)__popc(peers));
    }
}

__global__ void __launch_bounds__(96) k_score(const float* __restrict__ pred)
{
    __shared__ float tile[3][2720];        // 3 warps x 32 anchors x 85 floats

    int b = blockIdx.y;
    int w = threadIdx.x >> 5, l = threadIdx.x & 31;

    int base = blockIdx.x * 96 + w * 32;                 // 1050*96 == 100800 exactly
    const float4* p4 = (const float4*)(pred + ((size_t)b * NANCH + base) * 85);
    float4* t4 = (float4*)tile[w];
#pragma unroll
    for (int k = 0; k < 21; ++k) t4[k * 32 + l] = p4[k * 32 + l];
    if (l < 8) t4[672 + l] = p4[672 + l];                // 680 float4 = 2720 floats
    __syncwarp();                                        // per-warp tile, warp-local

    const float* row = &tile[w][l * 85];                 // stride 85: conflict-free
    float obj = row[4];

    // 4 independent strict-> chains merged by (value, lower index) ==
    // min-index-of-max == reference first-occurrence argmax
    float v0 = __fmul_rn(row[5], obj);     int i0 = 0;
    float v1 = __fmul_rn(row[6], obj);     int i1 = 1;
    float v2 = __fmul_rn(row[7], obj);     int i2 = 2;
    float v3 = __fmul_rn(row[8], obj);     int i3 = 3;
#pragma unroll
    for (int t = 1; t < 20; ++t) {
        int c = 4 * t;
        float a  = __fmul_rn(row[5 + c], obj);
        float bq = __fmul_rn(row[6 + c], obj);
        float cq = __fmul_rn(row[7 + c], obj);
        float dq = __fmul_rn(row[8 + c], obj);
        if (a  > v0) { v0 = a;  i0 = c;     }
        if (bq > v1) { v1 = bq; i1 = c + 1; }
        if (cq > v2) { v2 = cq; i2 = c + 2; }
        if (dq > v3) { v3 = dq; i3 = c + 3; }
    }
    float best = v0; int bi = i0;
    if (v1 > best || (v1 == best && i1 < bi)) { best = v1; bi = i1; }
    if (v2 > best || (v2 == best && i2 < bi)) { best = v2; bi = i2; }
    if (v3 > best || (v3 == best && i3 < bi)) { best = v3; bi = i3; }

    bool  valid = (obj > 0.25f) && (best > 0.25f);
    float sm    = valid ? best : -1.0f;
    int   sb    = __float_as_int(sm);
    unsigned u  = (unsigned)sb ^ ((sb < 0) ? 0xFFFFFFFFu : 0x80000000u);
    int n = base + l;
    g_ukey[b][n] = u;
    g_cls [b][n] = (unsigned char)bi;

    // windowed histogram: VALID keys only (valid => score>0.25 => bin >= HBASE)
    unsigned idx = (u >> 16) - HBASE;
    if (idx > HBINS - 1) idx = HBINS - 1;                // catch-all (safety)
    gadd(&g_histS[b][0], idx, valid);
}

// ---------------- kernel 2: select + sort + gather + lazy-mask NMS -----------
struct SmemB {
    ull sel[2048];                      // selected keys; sort buffer 0 (A|B)
    ull sb2[2048];                      // sort buffer 1
    float s0[KPRE], s1[KPRE], s2[KPRE], s3[KPRE], sar[KPRE];  // offset boxes
    float bx1[KPRE], by1[KPRE], bx2[KPRE], by2[KPRE];         // raw boxes
    float ssc[KPRE], scf[KPRE];
    unsigned hs[HBINS];                 // windowed histogram copy
    unsigned smask[32][32];             // lazy mask chunk: 32 rows x 32 words
    unsigned sres[2];
    int list[MAXDET];
    int cnt, skc;
};

__device__ __forceinline__ ull umaxll(ull a, ull b) { return a > b ? a : b; }
__device__ __forceinline__ ull uminll(ull a, ull b) { return a < b ? a : b; }

__global__ void __launch_bounds__(1024) k_nms(const float* __restrict__ pred,
                                              float* __restrict__ out)
{
    extern __shared__ unsigned char dyn[];
    SmemB* sm = (SmemB*)dyn;

    int b = blockIdx.x, tid = threadIdx.x;
    int l = tid & 31, warp = tid >> 5;
    const uint4* uk4 = (const uint4*)&g_ukey[b][0];

    // ---- threshold: load window hist, self-zero, serial descend (512 bins) ---
    if (tid == 0) { sm->cnt = 0; sm->skc = 0; }
    if (tid < HBINS) {
        unsigned h = g_histS[b][tid];
        sm->hs[tid] = h;
        g_histS[b][tid] = 0;                           // self-zero for next run
    }
    __syncthreads();
    if (tid == 0) {
        unsigned acc = 0;
        int bin = HBINS - 1;
        while (bin > 0 && acc + sm->hs[bin] < KPRE) { acc += sm->hs[bin]; --bin; }
        sm->sres[0] = (unsigned)bin;
    }
    __syncthreads();
    unsigned uthr = (HBASE + sm->sres[0]) << 16;       // select keys u >= uthr

    // ---- single scan (MLP=4): append ALL keys >= uthr (order-free) ----
    for (int it = 0; it < 7; ++it) {                   // 7*4096 = 28672 >= 25200
        uint4 q[4]; bool a4[4];
#pragma unroll
        for (int s = 0; s < 4; ++s) {
            int t = it * 4096 + s * 1024 + tid;
            a4[s] = t < N4;
            q[s] = a4[s] ? uk4[t] : make_uint4(0u, 0u, 0u, 0u);
        }
#pragma unroll
        for (int s = 0; s < 4; ++s) {
            int t = it * 4096 + s * 1024 + tid;
            unsigned uu[4] = {q[s].x, q[s].y, q[s].z, q[s].w};
            bool h[4];
            int c = 0;
#pragma unroll
            for (int j = 0; j < 4; ++j) { h[j] = a4[s] && (uu[j] >= uthr); c += h[j]; }
            int pre = c;
#pragma unroll
            for (int o = 1; o < 32; o <<= 1) {
                int y = __shfl_up_sync(0xFFFFFFFFu, pre, o);
                if (l >= o) pre += y;
            }
            int tot = __shfl_sync(0xFFFFFFFFu, pre, 31);
            if (tot > 0) {
                int base2 = 0;
                if (l == 31) base2 = atomicAdd(&sm->cnt, tot);
                base2 = __shfl_sync(0xFFFFFFFFu, base2, 31);
                int p = base2 + pre - c;
#pragma unroll
                for (int j = 0; j < 4; ++j)
                    if (h[j]) {
                        if (p < 2048)
                            sm->sel[p] = ((ull)uu[j] << 32) | (unsigned)(~(4 * t + j));
                        p++;
                    }
            }
        }
    }
    __syncthreads();
    int total = sm->cnt; if (total > 2048) total = 2048;
    for (int i = tid; i < 2048; i += 1024)
        if (i >= total) sm->sel[i] = 0;                // pads sort to the bottom
    __syncthreads();

    // ---- bitonic sort of 2048 keys, descending (value, then smaller index) --
    ull kA = sm->sel[tid], kB = sm->sel[tid + 1024];
    int cur = 0;
    for (int k = 2; k <= 1024; k <<= 1) {
        bool dA = ((tid & k) == 0);
        bool dB = (((tid + 1024) & k) == 0);           // differs only at k=1024
        for (int j = k >> 1; j >= 32; j >>= 1) {
            ull* B = cur ? sm->sb2 : sm->sel;
            B[tid] = kA; B[tid + 1024] = kB;
            __syncthreads();
            ull oA = B[tid ^ j], oB = B[(tid ^ j) + 1024];
            bool lower = (tid & j) == 0;
            kA = (lower == dA) ? umaxll(kA, oA) : uminll(kA, oA);
            kB = (lower == dB) ? umaxll(kB, oB) : uminll(kB, oB);
            cur ^= 1;
        }
        int j0 = (k >> 1) < 16 ? (k >> 1) : 16;
        for (int j = j0; j >= 1; j >>= 1) {
            ull oA = __shfl_xor_sync(0xFFFFFFFFu, kA, j);
            ull oB = __shfl_xor_sync(0xFFFFFFFFu, kB, j);
            bool lower = (tid & j) == 0;
            kA = (lower == dA) ? umaxll(kA, oA) : uminll(kA, oA);
            kB = (lower == dB) ? umaxll(kB, oB) : uminll(kB, oB);
        }
    }
    {   // final stage k=2048: descending everywhere
        ull hi = umaxll(kA, kB), lo = uminll(kA, kB);  // j=1024: in-thread pair
        kA = hi; kB = lo;
        for (int j = 512; j >= 32; j >>= 1) {
            ull* B = cur ? sm->sb2 : sm->sel;
            B[tid] = kA; B[tid + 1024] = kB;
            __syncthreads();
            ull oA = B[tid ^ j], oB = B[(tid ^ j) + 1024];
            bool lower = (tid & j) == 0;
            kA = lower ? umaxll(kA, oA) : uminll(kA, oA);
            kB = lower ? umaxll(kB, oB) : uminll(kB, oB);
            cur ^= 1;
        }
#pragma unroll
        for (int j = 16; j >= 1; j >>= 1) {
            ull oA = __shfl_xor_sync(0xFFFFFFFFu, kA, j);
            ull oB = __shfl_xor_sync(0xFFFFFFFFu, kB, j);
            bool lower = (tid & j) == 0;
            kA = lower ? umaxll(kA, oA) : uminll(kA, oA);
            kB = lower ? umaxll(kB, oB) : uminll(kB, oB);
        }
    }
    // kA now holds rank-tid key (descending) == reference top_k order

    // ---- gather boxes / class / score into SMEM (bit-exact arithmetic) ----
    {
        unsigned n = ~((unsigned)(kA & 0xFFFFFFFFull));
        if (n >= NANCH) n = 0;                          // pad safety (never real)
        unsigned u = (unsigned)(kA >> 32);
        unsigned sb = (u & 0x80000000u) ? (u ^ 0x80000000u) : ~u;
        float sc = __int_as_float((int)sb);
        const float* p = pred + ((size_t)b * NANCH + n) * 85;
        float cx = __ldg(p), cy = __ldg(p + 1), w = __ldg(p + 2), h = __ldg(p + 3);
        float hw = __fmul_rn(w, 0.5f), hh = __fmul_rn(h, 0.5f);
        float x1 = __fsub_rn(cx, hw), y1 = __fsub_rn(cy, hh);
        float x2 = __fadd_rn(cx, hw), y2 = __fadd_rn(cy, hh);
        float cf = (float)(int)g_cls[b][n];
        float off = __fmul_rn(cf, 7680.0f);
        float o0 = __fadd_rn(x1, off), o1 = __fadd_rn(y1, off);
        float o2 = __fadd_rn(x2, off), o3 = __fadd_rn(y2, off);
        sm->bx1[tid] = x1; sm->by1[tid] = y1; sm->bx2[tid] = x2; sm->by2[tid] = y2;
        sm->s0[tid] = o0;  sm->s1[tid] = o1;  sm->s2[tid] = o2;  sm->s3[tid] = o3;
        sm->sar[tid] = __fmul_rn(__fsub_rn(o2, o0), __fsub_rn(o3, o1));
        sm->ssc[tid] = sc;
        sm->scf[tid] = cf;
    }
    int V = __syncthreads_count(sm->ssc[tid] > 0.0f);  // valid == prefix (sorted)

    // ---- lazy mask + greedy scan, 32 rows per chunk, early exit at 100 ----
    unsigned kept = 0;
    int kc = 0;
    for (int c = 0; c < 32; ++c) {
        {
            int i = (c << 5) + warp;
            float a0 = sm->s0[i], a1 = sm->s1[i], a2 = sm->s2[i], a3 = sm->s3[i];
            float aa = sm->sar[i];
            for (int t = 0; t <= c; ++t) {
                int j = (t << 5) + l;
                bool bit = false;
                if (j < i) {
                    float xx1 = fmaxf(a0, sm->s0[j]);
                    float yy1 = fmaxf(a1, sm->s1[j]);
                    float xx2 = fminf(a2, sm->s2[j]);
                    float yy2 = fminf(a3, sm->s3[j]);
                    float ww = fmaxf(__fsub_rn(xx2, xx1), 0.0f);
                    float hh = fmaxf(__fsub_rn(yy2, yy1), 0.0f);
                    float inter = __fmul_rn(ww, hh);
                    float uni = __fsub_rn(__fadd_rn(aa, sm->sar[j]), inter);
                    float iou = __fdiv_rn(inter, __fadd_rn(uni, 1e-7f));
                    bit = iou > 0.45f;
                }
                unsigned word = __ballot_sync(0xFFFFFFFFu, bit);
                if (l == 0) sm->smask[warp][t] = word;
            }
        }
        __syncthreads();

        if (tid < 32) {                     // warp 0: scan this chunk
            unsigned mA[32];
#pragma unroll
            for (int k = 0; k < 32; ++k) mA[k] = (l <= c) ? sm->smask[k][l] : 0u;
            unsigned hv = 0;
#pragma unroll
            for (int k = 0; k < 32; ++k) hv |= ((mA[k] & kept) ? 1u : 0u) << k;
            unsigned grpHit = __reduce_or_sync(0xFFFFFFFFu, hv);
            int add = 0;
            if (l == c) {
                unsigned newBits = 0;
                int kcl = kc;
#pragma unroll
                for (int k = 0; k < 32; ++k) {
                    int i = (c << 5) + k;
                    bool sup = ((grpHit >> k) & 1u) != 0u || (mA[k] & newBits) != 0u;
                    if (i < V && !sup) {
                        newBits |= 1u << k;
                        if (kcl < MAXDET) sm->list[kcl] = i;
                        kcl++; add++;
                    }
                }
                kept |= newBits;
            }
            kc += __shfl_sync(0xFFFFFFFFu, add, c);
            if (l == 0) sm->skc = kc;
        }
        __syncthreads();
        if (sm->skc >= MAXDET) break;       // only first 100 kept observable
        if (((c + 1) << 5) >= V) break;     // remaining rows all invalid
    }

    // ---- output (zeros beyond K; replaces memset) ----
    int K = sm->skc; if (K > MAXDET) K = MAXDET;
    for (int s = tid; s < MAXDET; s += 1024) {
        float v0 = 0.f, v1 = 0.f, v2 = 0.f, v3 = 0.f, v4 = 0.f, v5 = 0.f;
        if (s < K) {
            int i = sm->list[s];
            v0 = sm->bx1[i]; v1 = sm->by1[i]; v2 = sm->bx2[i]; v3 = sm->by2[i];
            v4 = sm->ssc[i]; v5 = sm->scf[i];
        }
        float* o = out + ((size_t)(b * MAXDET + s)) * 6;
        o[0] = v0; o[1] = v1; o[2] = v2; o[3] = v3; o[4] = v4; o[5] = v5;
    }
}

// ---------------- launch ------------------------------------------------------
extern "C" void kernel_launch(void* const* d_in, const int* in_sizes, int n_in,
                              void* d_out, int out_size)
{
    const float* pred = (const float*)d_in[0];
    float* out = (float*)d_out;

    static int smem_set = 0;
    if (!smem_set) {
        cudaFuncSetAttribute(k_nms, cudaFuncAttributeMaxDynamicSharedMemorySize,
                             (int)sizeof(SmemB));
        smem_set = 1;
    }
    k_score<<<dim3(1050, BATCH), 96>>>(pred);
    k_nms  <<<BATCH, 1024, sizeof(SmemB)>>>(pred, out);
}

// round 15
// speedup vs baseline: 1.7106x; 1.0333x over previous
#include <cuda_runtime.h>
#include <stdint.h>

#define BATCH  8
#define NANCH  100800
#define KPRE   1024
#define MAXDET 100
#define N4     (NANCH / 4)              // 25200
#define HBASE  0xBE80u                  // bin of smallest possible valid score (>0.25)
#define HBINS  512                      // window covers score (0.25, ~4); top bin = catch-all
#define UCUT   0xBF400000u              // static candidate cut (score ~0.75)

typedef unsigned long long ull;

// ---------------- scratch (static device memory; no runtime allocation) ------
__device__ unsigned int  g_ukey [BATCH][NANCH];
__device__ unsigned char g_cls  [BATCH][NANCH];
__device__ unsigned int  g_histS[BATCH][HBINS];    // windowed 16-bit hist (self-zero)
__device__ ull           g_candK[BATCH][NANCH];    // pre-cut candidate keys
__device__ unsigned int  g_ccnt [BATCH];           // candidate counts (self-zero)

// ---------------- kernel 1: coalesced score / argmax / key / histogram -------
__device__ __forceinline__ void gadd(unsigned* dst, unsigned bin, bool q)
{
    unsigned qm = __ballot_sync(0xFFFFFFFFu, q);
    if (q) {
        unsigned peers = __match_any_sync(qm, bin);
        int ld = __ffs(peers) - 1;
        if ((int)(threadIdx.x & 31) == ld) atomicAdd(&dst[bin], (unsigned)__popc(peers));
    }
}

__global__ void __launch_bounds__(96) k_score(const float* __restrict__ pred)
{
    __shared__ float tile[3][2720];        // 3 warps x 32 anchors x 85 floats

    int b = blockIdx.y;
    int w = threadIdx.x >> 5, l = threadIdx.x & 31;

    int base = blockIdx.x * 96 + w * 32;                 // 1050*96 == 100800 exactly
    const float4* p4 = (const float4*)(pred + ((size_t)b * NANCH + base) * 85);
    float4* t4 = (float4*)tile[w];
#pragma unroll
    for (int k = 0; k < 21; ++k) t4[k * 32 + l] = p4[k * 32 + l];
    if (l < 8) t4[672 + l] = p4[672 + l];                // 680 float4 = 2720 floats
    __syncwarp();                                        // per-warp tile, warp-local

    const float* row = &tile[w][l * 85];                 // stride 85: conflict-free
    float obj = row[4];

    // 4 independent strict-> chains merged by (value, lower index) ==
    // min-index-of-max == reference first-occurrence argmax
    float v0 = __fmul_rn(row[5], obj);     int i0 = 0;
    float v1 = __fmul_rn(row[6], obj);     int i1 = 1;
    float v2 = __fmul_rn(row[7], obj);     int i2 = 2;
    float v3 = __fmul_rn(row[8], obj);     int i3 = 3;
#pragma unroll
    for (int t = 1; t < 20; ++t) {
        int c = 4 * t;
        float a  = __fmul_rn(row[5 + c], obj);
        float bq = __fmul_rn(row[6 + c], obj);
        float cq = __fmul_rn(row[7 + c], obj);
        float dq = __fmul_rn(row[8 + c], obj);
        if (a  > v0) { v0 = a;  i0 = c;     }
        if (bq > v1) { v1 = bq; i1 = c + 1; }
        if (cq > v2) { v2 = cq; i2 = c + 2; }
        if (dq > v3) { v3 = dq; i3 = c + 3; }
    }
    float best = v0; int bi = i0;
    if (v1 > best || (v1 == best && i1 < bi)) { best = v1; bi = i1; }
    if (v2 > best || (v2 == best && i2 < bi)) { best = v2; bi = i2; }
    if (v3 > best || (v3 == best && i3 < bi)) { best = v3; bi = i3; }

    bool  valid = (obj > 0.25f) && (best > 0.25f);
    float sm    = valid ? best : -1.0f;
    int   sb    = __float_as_int(sm);
    unsigned u  = (unsigned)sb ^ ((sb < 0) ? 0xFFFFFFFFu : 0x80000000u);
    int n = base + l;
    g_ukey[b][n] = u;
    g_cls [b][n] = (unsigned char)bi;

    // windowed histogram: VALID keys only (valid => score>0.25 => bin >= HBASE)
    unsigned idx = (u >> 16) - HBASE;
    if (idx > HBINS - 1) idx = HBINS - 1;                // catch-all (safety)
    gadd(&g_histS[b][0], idx, valid);

    // pre-cut candidate append (warp-aggregated): keys above static cut
    bool app = valid && (u >= UCUT);
    unsigned bal = __ballot_sync(0xFFFFFFFFu, app);
    if (bal) {
        int base2 = 0;
        if (l == __ffs(bal) - 1) base2 = (int)atomicAdd(&g_ccnt[b], (unsigned)__popc(bal));
        base2 = __shfl_sync(0xFFFFFFFFu, base2, __ffs(bal) - 1);
        if (app) {
            int p = base2 + __popc(bal & ((1u << l) - 1));
            if (p < NANCH) g_candK[b][p] = ((ull)u << 32) | (unsigned)(~n);
        }
    }
}

// ---------------- kernel 2: select + sort + gather + lazy-mask NMS -----------
struct SmemB {
    ull sel[2048];                      // selected keys; sort buffer 0 (A|B)
    ull sb2[2048];                      // sort buffer 1
    float s0[KPRE], s1[KPRE], s2[KPRE], s3[KPRE], sar[KPRE];  // offset boxes
    float bx1[KPRE], by1[KPRE], bx2[KPRE], by2[KPRE];         // raw boxes
    float ssc[KPRE], scf[KPRE];
    unsigned hs[HBINS];                 // windowed histogram copy
    unsigned smask[32][32];             // lazy mask chunk: 32 rows x 32 words
    unsigned sres[2];
    int list[MAXDET];
    int cnt, skc, ccnt;
};

__device__ __forceinline__ ull umaxll(ull a, ull b) { return a > b ? a : b; }
__device__ __forceinline__ ull uminll(ull a, ull b) { return a < b ? a : b; }

// warp-aggregated ballot/popc append of one predicated key into sm->sel
__device__ __forceinline__ void sel_append(SmemB* sm, bool ok, ull key, int l)
{
    unsigned bal = __ballot_sync(0xFFFFFFFFu, ok);
    if (bal) {
        int base2 = 0;
        if (l == 0) base2 = atomicAdd(&sm->cnt, __popc(bal));
        base2 = __shfl_sync(0xFFFFFFFFu, base2, 0);
        if (ok) {
            int p = base2 + __popc(bal & ((1u << l) - 1));
            if (p < 2048) sm->sel[p] = key;
        }
    }
}

__global__ void __launch_bounds__(1024) k_nms(const float* __restrict__ pred,
                                              float* __restrict__ out)
{
    extern __shared__ unsigned char dyn[];
    SmemB* sm = (SmemB*)dyn;

    int b = blockIdx.x, tid = threadIdx.x;
    int l = tid & 31, warp = tid >> 5;

    // ---- threshold: load window hist, self-zero, serial descend (512 bins) ---
    if (tid == 0) {
        sm->cnt = 0; sm->skc = 0;
        sm->ccnt = (int)g_ccnt[b];
        g_ccnt[b] = 0;                                 // self-zero for next run
    }
    if (tid < HBINS) {
        unsigned h = g_histS[b][tid];
        sm->hs[tid] = h;
        g_histS[b][tid] = 0;                           // self-zero for next run
    }
    __syncthreads();
    if (tid == 0) {
        unsigned acc = 0;
        int bin = HBINS - 1;
        while (bin > 0 && acc + sm->hs[bin] < KPRE) { acc += sm->hs[bin]; --bin; }
        sm->sres[0] = (unsigned)bin;
    }
    __syncthreads();
    unsigned uthr = (HBASE + sm->sres[0]) << 16;       // select keys u >= uthr

    if (uthr >= UCUT) {
        // ---- FAST scan: candidate list only (complete since uthr >= UCUT) ----
        const ull* cnd = &g_candK[b][0];
        int cc = sm->ccnt; if (cc > NANCH) cc = NANCH;
        int iters = (cc + 4095) >> 12;                 // uniform across block
        for (int it = 0; it < iters; ++it) {
            ull k4[4]; bool a4[4];
#pragma unroll
            for (int s = 0; s < 4; ++s) {
                int t = (it << 12) + (s << 10) + tid;
                a4[s] = t < cc;
                k4[s] = a4[s] ? cnd[t] : 0ull;
            }
#pragma unroll
            for (int s = 0; s < 4; ++s)
                sel_append(sm, a4[s] && ((unsigned)(k4[s] >> 32) >= uthr), k4[s], l);
        }
    } else {
        // ---- FALLBACK: full ukey scan (always correct) ----
        const uint4* uk4 = (const uint4*)&g_ukey[b][0];
        for (int it = 0; it < 7; ++it) {               // 7*4096 = 28672 >= 25200
            uint4 q[4]; bool a4[4];
#pragma unroll
            for (int s = 0; s < 4; ++s) {
                int t = it * 4096 + s * 1024 + tid;
                a4[s] = t < N4;
                q[s] = a4[s] ? uk4[t] : make_uint4(0u, 0u, 0u, 0u);
            }
#pragma unroll
            for (int s = 0; s < 4; ++s) {
                int t = it * 4096 + s * 1024 + tid;
                unsigned uu[4] = {q[s].x, q[s].y, q[s].z, q[s].w};
#pragma unroll
                for (int j = 0; j < 4; ++j) {
                    bool ok = a4[s] && (uu[j] >= uthr);
                    ull key = ((ull)uu[j] << 32) | (unsigned)(~(4 * t + j));
                    sel_append(sm, ok, key, l);
                }
            }
        }
    }
    __syncthreads();
    int total = sm->cnt; if (total > 2048) total = 2048;
    for (int i = tid; i < 2048; i += 1024)
        if (i >= total) sm->sel[i] = 0;                // pads sort to the bottom
    __syncthreads();

    // ---- bitonic sort of 2048 keys, descending (value, then smaller index) --
    ull kA = sm->sel[tid], kB = sm->sel[tid + 1024];
    int cur = 0;
    for (int k = 2; k <= 1024; k <<= 1) {
        bool dA = ((tid & k) == 0);
        bool dB = (((tid + 1024) & k) == 0);           // differs only at k=1024
        for (int j = k >> 1; j >= 32; j >>= 1) {
            ull* B = cur ? sm->sb2 : sm->sel;
            B[tid] = kA; B[tid + 1024] = kB;
            __syncthreads();
            ull oA = B[tid ^ j], oB = B[(tid ^ j) + 1024];
            bool lower = (tid & j) == 0;
            kA = (lower == dA) ? umaxll(kA, oA) : uminll(kA, oA);
            kB = (lower == dB) ? umaxll(kB, oB) : uminll(kB, oB);
            cur ^= 1;
        }
        int j0 = (k >> 1) < 16 ? (k >> 1) : 16;
        for (int j = j0; j >= 1; j >>= 1) {
            ull oA = __shfl_xor_sync(0xFFFFFFFFu, kA, j);
            ull oB = __shfl_xor_sync(0xFFFFFFFFu, kB, j);
            bool lower = (tid & j) == 0;
            kA = (lower == dA) ? umaxll(kA, oA) : uminll(kA, oA);
            kB = (lower == dB) ? umaxll(kB, oB) : uminll(kB, oB);
        }
    }
    {   // final stage k=2048: descending everywhere
        ull hi = umaxll(kA, kB), lo = uminll(kA, kB);  // j=1024: in-thread pair
        kA = hi; kB = lo;
        for (int j = 512; j >= 32; j >>= 1) {
            ull* B = cur ? sm->sb2 : sm->sel;
            B[tid] = kA; B[tid + 1024] = kB;
            __syncthreads();
            ull oA = B[tid ^ j], oB = B[(tid ^ j) + 1024];
            bool lower = (tid & j) == 0;
            kA = lower ? umaxll(kA, oA) : uminll(kA, oA);
            kB = lower ? umaxll(kB, oB) : uminll(kB, oB);
            cur ^= 1;
        }
#pragma unroll
        for (int j = 16; j >= 1; j >>= 1) {
            ull oA = __shfl_xor_sync(0xFFFFFFFFu, kA, j);
            ull oB = __shfl_xor_sync(0xFFFFFFFFu, kB, j);
            bool lower = (tid & j) == 0;
            kA = lower ? umaxll(kA, oA) : uminll(kA, oA);
            kB = lower ? umaxll(kB, oB) : uminll(kB, oB);
        }
    }
    // kA now holds rank-tid key (descending) == reference top_k order

    // ---- gather boxes / class / score into SMEM (bit-exact arithmetic) ----
    {
        unsigned n = ~((unsigned)(kA & 0xFFFFFFFFull));
        if (n >= NANCH) n = 0;                          // pad safety (never real)
        unsigned u = (unsigned)(kA >> 32);
        unsigned sb = (u & 0x80000000u) ? (u ^ 0x80000000u) : ~u;
        float sc = __int_as_float((int)sb);
        const float* p = pred + ((size_t)b * NANCH + n) * 85;
        float cx = __ldg(p), cy = __ldg(p + 1), w = __ldg(p + 2), h = __ldg(p + 3);
        float hw = __fmul_rn(w, 0.5f), hh = __fmul_rn(h, 0.5f);
        float x1 = __fsub_rn(cx, hw), y1 = __fsub_rn(cy, hh);
        float x2 = __fadd_rn(cx, hw), y2 = __fadd_rn(cy, hh);
        float cf = (float)(int)g_cls[b][n];
        float off = __fmul_rn(cf, 7680.0f);
        float o0 = __fadd_rn(x1, off), o1 = __fadd_rn(y1, off);
        float o2 = __fadd_rn(x2, off), o3 = __fadd_rn(y2, off);
        sm->bx1[tid] = x1; sm->by1[tid] = y1; sm->bx2[tid] = x2; sm->by2[tid] = y2;
        sm->s0[tid] = o0;  sm->s1[tid] = o1;  sm->s2[tid] = o2;  sm->s3[tid] = o3;
        sm->sar[tid] = __fmul_rn(__fsub_rn(o2, o0), __fsub_rn(o3, o1));
        sm->ssc[tid] = sc;
        sm->scf[tid] = cf;
    }
    int V = __syncthreads_count(sm->ssc[tid] > 0.0f);  // valid == prefix (sorted)

    // ---- lazy mask + greedy scan, 32 rows per chunk, early exit at 100 ----
    unsigned kept = 0;
    int kc = 0;
    for (int c = 0; c < 32; ++c) {
        {
            int i = (c << 5) + warp;
            float a0 = sm->s0[i], a1 = sm->s1[i], a2 = sm->s2[i], a3 = sm->s3[i];
            float aa = sm->sar[i];
            for (int t = 0; t <= c; ++t) {
                int j = (t << 5) + l;
                bool bit = false;
                if (j < i) {
                    float xx1 = fmaxf(a0, sm->s0[j]);
                    float yy1 = fmaxf(a1, sm->s1[j]);
                    float xx2 = fminf(a2, sm->s2[j]);
                    float yy2 = fminf(a3, sm->s3[j]);
                    float ww = fmaxf(__fsub_rn(xx2, xx1), 0.0f);
                    float hh = fmaxf(__fsub_rn(yy2, yy1), 0.0f);
                    float inter = __fmul_rn(ww, hh);
                    float uni = __fsub_rn(__fadd_rn(aa, sm->sar[j]), inter);
                    float iou = __fdiv_rn(inter, __fadd_rn(uni, 1e-7f));
                    bit = iou > 0.45f;
                }
                unsigned word = __ballot_sync(0xFFFFFFFFu, bit);
                if (l == 0) sm->smask[warp][t] = word;
            }
        }
        __syncthreads();

        if (tid < 32) {                     // warp 0: scan this chunk
            unsigned mA[32];
#pragma unroll
            for (int k = 0; k < 32; ++k) mA[k] = (l <= c) ? sm->smask[k][l] : 0u;
            unsigned hv = 0;
#pragma unroll
            for (int k = 0; k < 32; ++k) hv |= ((mA[k] & kept) ? 1u : 0u) << k;
            unsigned grpHit = __reduce_or_sync(0xFFFFFFFFu, hv);
            int add = 0;
            if (l == c) {
                unsigned newBits = 0;
                int kcl = kc;
#pragma unroll
                for (int k = 0; k < 32; ++k) {
                    int i = (c << 5) + k;
                    bool sup = ((grpHit >> k) & 1u) != 0u || (mA[k] & newBits) != 0u;
                    if (i < V && !sup) {
                        newBits |= 1u << k;
                        if (kcl < MAXDET) sm->list[kcl] = i;
                        kcl++; add++;
                    }
                }
                kept |= newBits;
            }
            kc += __shfl_sync(0xFFFFFFFFu, add, c);
            if (l == 0) sm->skc = kc;
        }
        __syncthreads();
        if (sm->skc >= MAXDET) break;       // only first 100 kept observable
        if (((c + 1) << 5) >= V) break;     // remaining rows all invalid
    }

    // ---- output (zeros beyond K; replaces memset) ----
    int K = sm->skc; if (K > MAXDET) K = MAXDET;
    for (int s = tid; s < MAXDET; s += 1024) {
        float v0 = 0.f, v1 = 0.f, v2 = 0.f, v3 = 0.f, v4 = 0.f, v5 = 0.f;
        if (s < K) {
            int i = sm->list[s];
            v0 = sm->bx1[i]; v1 = sm->by1[i]; v2 = sm->bx2[i]; v3 = sm->by2[i];
            v4 = sm->ssc[i]; v5 = sm->scf[i];
        }
        float* o = out + ((size_t)(b * MAXDET + s)) * 6;
        o[0] = v0; o[1] = v1; o[2] = v2; o[3] = v3; o[4] = v4; o[5] = v5;
    }
}

// ---------------- launch ------------------------------------------------------
extern "C" void kernel_launch(void* const* d_in, const int* in_sizes, int n_in,
                              void* d_out, int out_size)
{
    const float* pred = (const float*)d_in[0];
    float* out = (float*)d_out;

    static int smem_set = 0;
    if (!smem_set) {
        cudaFuncSetAttribute(k_nms, cudaFuncAttributeMaxDynamicSharedMemorySize,
                             (int)sizeof(SmemB));
        smem_set = 1;
    }
    k_score<<<dim3(1050, BATCH), 96>>>(pred);
    k_nms  <<<BATCH, 1024, sizeof(SmemB)>>>(pred, out);
}